// round 6
// baseline (speedup 1.0000x reference)
#include <cuda_runtime.h>
#include <cstdint>

#define NN_MAX 50000
#define NE_MAX 800000
#define FH 64

// Scratch
__device__ float g_deg[NN_MAX];
__device__ float g_norm[NE_MAX];
__device__ float g_tx1[NN_MAX * FH];
__device__ float g_p2[NN_MAX * FH];
__device__ float g_Wc[192 * 136];   // combined weights, [k][n] stride 136, tf32-rounded

__device__ __forceinline__ void red_add_v4(float* a, float x, float y, float z, float w) {
    asm volatile("red.global.add.v4.f32 [%0], {%1,%2,%3,%4};"
                 :: "l"(a), "f"(x), "f"(y), "f"(z), "f"(w) : "memory");
}
__device__ __forceinline__ uint32_t f2tf32(float f) {
    uint32_t u;
    asm("cvt.rna.tf32.f32 %0, %1;" : "=r"(u) : "f"(f));
    return u;
}
__device__ __forceinline__ float fast_sigmoid(float x) { return 1.f / (1.f + __expf(-x)); }
__device__ __forceinline__ float fast_tanh(float x) {
    float t = __expf(-2.f * fabsf(x));
    float r = (1.f - t) / (1.f + t);
    return copysignf(r, x);
}

// ---------------------------------------------------------------------------
// Fused: blocks [0, nbDeg) do degree atomics; blocks [nbDeg, ...) build g_Wc.
__global__ void k_deg_comb(const int* __restrict__ row, const float* __restrict__ w, int ne,
                           const float* __restrict__ Wxz, const float* __restrict__ Wxh) {
    int nbDeg = (ne + 255) >> 8;
    if ((int)blockIdx.x < nbDeg) {
        int e = blockIdx.x * 256 + threadIdx.x;
        if (e < ne) atomicAdd(g_deg + row[e], w[e]);
    } else {
        int t = (blockIdx.x - nbDeg) * 256 + threadIdx.x;
        if (t < 192 * 128) {
            int k = t >> 7, j = t & 127;
            const float* W = (j < 64) ? Wxz : Wxh;
            int jj = j & 63;
            float v;
            if (k < 64)       v = W[k * 64 + jj] - W[2 * 4096 + k * 64 + jj];
            else if (k < 128) v = W[4096 + (k - 64) * 64 + jj];
            else              v = 2.f * W[2 * 4096 + (k - 128) * 64 + jj];
            g_Wc[k * 136 + j] = __uint_as_float(f2tf32(v));
        }
    }
}

// pass 0: 4 threads/edge; norm computed inline (x4 redundant), stored at q==0.
__global__ void k_prop0(const float* __restrict__ x, const int* __restrict__ row,
                        const int* __restrict__ col, const float* __restrict__ w, int ne) {
    int t = blockIdx.x * blockDim.x + threadIdx.x;
    int e = t >> 2, q = t & 3;
    if (e >= ne) return;
    int r = row[e], c = col[e];
    float dr = g_deg[r], dc = g_deg[c];
    float ir = dr > 0.f ? rsqrtf(dr) : 0.f;
    float ic = dc > 0.f ? rsqrtf(dc) : 0.f;
    float nm = -ir * w[e] * ic;
    if (q == 0) g_norm[e] = nm;
    const float* sr = x + r * FH;
    float* dst = g_tx1 + c * FH;
    float4 v0 = *(const float4*)(sr + (q)      * 4);
    float4 v1 = *(const float4*)(sr + (q + 4)  * 4);
    float4 v2 = *(const float4*)(sr + (q + 8)  * 4);
    float4 v3 = *(const float4*)(sr + (q + 12) * 4);
    red_add_v4(dst + (q)      * 4, nm * v0.x, nm * v0.y, nm * v0.z, nm * v0.w);
    red_add_v4(dst + (q + 4)  * 4, nm * v1.x, nm * v1.y, nm * v1.z, nm * v1.w);
    red_add_v4(dst + (q + 8)  * 4, nm * v2.x, nm * v2.y, nm * v2.z, nm * v2.w);
    red_add_v4(dst + (q + 12) * 4, nm * v3.x, nm * v3.y, nm * v3.z, nm * v3.w);
}

// pass 1: 4 threads/edge; tx1 -> p2 using stored norm.
__global__ void k_prop1(const int* __restrict__ row, const int* __restrict__ col, int ne) {
    int t = blockIdx.x * blockDim.x + threadIdx.x;
    int e = t >> 2, q = t & 3;
    if (e >= ne) return;
    float nm = g_norm[e];
    int r = row[e], c = col[e];
    const float* sr = g_tx1 + r * FH;
    float* dst = g_p2 + c * FH;
    float4 v0 = *(const float4*)(sr + (q)      * 4);
    float4 v1 = *(const float4*)(sr + (q + 4)  * 4);
    float4 v2 = *(const float4*)(sr + (q + 8)  * 4);
    float4 v3 = *(const float4*)(sr + (q + 12) * 4);
    red_add_v4(dst + (q)      * 4, nm * v0.x, nm * v0.y, nm * v0.z, nm * v0.w);
    red_add_v4(dst + (q + 4)  * 4, nm * v1.x, nm * v1.y, nm * v1.z, nm * v1.w);
    red_add_v4(dst + (q + 8)  * 4, nm * v2.x, nm * v2.y, nm * v2.z, nm * v2.w);
    red_add_v4(dst + (q + 12) * 4, nm * v3.x, nm * v3.y, nm * v3.z, nm * v3.w);
}

// ---------------------------------------------------------------------------
// k_final: per block 128 nodes; D[128x128] = A[128x192] @ B[192x128] via
// mma.sync.m16n8k8.tf32, then gates + head.
#define A_STR 196
#define B_STR 136
#define Y_STR 132
#define SM_BZ   0
#define SM_BH   256
#define SM_WLIN 512
#define SM_A    1024
#define SM_B    (SM_A + 128 * A_STR * 4)
#define SMEM_BYTES (SM_B + 192 * B_STR * 4)

__device__ __forceinline__ void mma8(float* c, const uint32_t* a, const uint32_t* b) {
    asm volatile("mma.sync.aligned.m16n8k8.row.col.f32.tf32.tf32.f32 "
                 "{%0,%1,%2,%3}, {%4,%5,%6,%7}, {%8,%9}, {%0,%1,%2,%3};"
                 : "+f"(c[0]), "+f"(c[1]), "+f"(c[2]), "+f"(c[3])
                 : "r"(a[0]), "r"(a[1]), "r"(a[2]), "r"(a[3]), "r"(b[0]), "r"(b[1]));
}

__global__ void __launch_bounds__(256, 1)
k_final(const float* __restrict__ x,
        const float* __restrict__ bxz, const float* __restrict__ bhz,
        const float* __restrict__ bxh, const float* __restrict__ bhh,
        const float* __restrict__ Wlin, const float* __restrict__ blin,
        float* __restrict__ out, int n) {
    extern __shared__ __align__(16) char smem[];
    float* sBz = (float*)(smem + SM_BZ);
    float* sBh = (float*)(smem + SM_BH);
    float* sWl = (float*)(smem + SM_WLIN);
    float* As  = (float*)(smem + SM_A);
    float* Bs  = (float*)(smem + SM_B);
    const uint32_t* Au = (const uint32_t*)As;
    const uint32_t* Bu = (const uint32_t*)Bs;

    int tid = threadIdx.x, wid = tid >> 5, lane = tid & 31;
    int blk = blockIdx.x;

    for (int t = tid; t < 6528; t += 256)
        ((float4*)Bs)[t] = ((const float4*)g_Wc)[t];

    for (int idx = tid; idx < 128 * 48; idx += 256) {
        int m = idx / 48, seg = idx % 48;
        int g = blk * 128 + m;
        float4 v = make_float4(0.f, 0.f, 0.f, 0.f);
        if (g < n) {
            const float* src = (seg < 16) ? (x + g * FH + seg * 4)
                             : (seg < 32) ? (g_tx1 + g * FH + (seg - 16) * 4)
                                          : (g_p2 + g * FH + (seg - 32) * 4);
            v = *(const float4*)src;
        }
        float4 o;
        o.x = __uint_as_float(f2tf32(v.x));
        o.y = __uint_as_float(f2tf32(v.y));
        o.z = __uint_as_float(f2tf32(v.z));
        o.w = __uint_as_float(f2tf32(v.w));
        *(float4*)(As + m * A_STR + seg * 4) = o;
    }

    if (tid < 64) {
        sBz[tid] = bxz[tid] + bhz[tid];
        sBh[tid] = bxh[tid] + bhh[tid];
    }
    if (tid < 128) sWl[tid] = Wlin[tid];
    __syncthreads();

    int mw = wid >> 2, nw = wid & 3;
    int g8 = lane >> 2, t4 = lane & 3;
    int m0 = mw * 64, n0 = nw * 32;

    float acc[4][4][4];
    #pragma unroll
    for (int mt = 0; mt < 4; ++mt)
        #pragma unroll
        for (int nt = 0; nt < 4; ++nt)
            #pragma unroll
            for (int e = 0; e < 4; ++e) acc[mt][nt][e] = 0.f;

    #pragma unroll 4
    for (int ks = 0; ks < 24; ++ks) {
        int k0 = ks * 8;
        uint32_t a[4][4];
        #pragma unroll
        for (int mt = 0; mt < 4; ++mt) {
            int r0 = m0 + mt * 16;
            a[mt][0] = Au[(r0 + g8)     * A_STR + k0 + t4];
            a[mt][1] = Au[(r0 + g8 + 8) * A_STR + k0 + t4];
            a[mt][2] = Au[(r0 + g8)     * A_STR + k0 + t4 + 4];
            a[mt][3] = Au[(r0 + g8 + 8) * A_STR + k0 + t4 + 4];
        }
        uint32_t b[4][2];
        #pragma unroll
        for (int nt = 0; nt < 4; ++nt) {
            int c0 = n0 + nt * 8;
            b[nt][0] = Bu[(k0 + t4)     * B_STR + c0 + g8];
            b[nt][1] = Bu[(k0 + t4 + 4) * B_STR + c0 + g8];
        }
        #pragma unroll
        for (int mt = 0; mt < 4; ++mt)
            #pragma unroll
            for (int nt = 0; nt < 4; ++nt)
                mma8(acc[mt][nt], a[mt], b[nt]);
    }
    __syncthreads();

    float* Ys = As;
    #pragma unroll
    for (int mt = 0; mt < 4; ++mt) {
        #pragma unroll
        for (int nt = 0; nt < 4; ++nt) {
            int r = m0 + mt * 16 + g8;
            int c = n0 + nt * 8 + 2 * t4;
            Ys[r * Y_STR + c]           = acc[mt][nt][0];
            Ys[r * Y_STR + c + 1]       = acc[mt][nt][1];
            Ys[(r + 8) * Y_STR + c]     = acc[mt][nt][2];
            Ys[(r + 8) * Y_STR + c + 1] = acc[mt][nt][3];
        }
    }
    __syncthreads();

    for (int t = tid; t < 128 * 64; t += 256) {
        int i = t >> 6, j = t & 63;
        float cz = Ys[i * Y_STR + j]      + sBz[j];
        float ch = Ys[i * Y_STR + 64 + j] + sBh[j];
        float z  = fast_sigmoid(cz);
        float ht = fast_tanh(ch);
        Ys[i * Y_STR + j] = fast_tanh((1.f - z) * ht);
    }
    __syncthreads();

    {
        int i = tid >> 1, c = tid & 1;
        int g = blk * 128 + i;
        if (g < n) {
            float s = blin[c];
            #pragma unroll 8
            for (int jj = 0; jj < 64; ++jj)
                s = fmaf(Ys[i * Y_STR + jj], sWl[2 * jj + c], s);
            out[g * 2 + c] = fast_sigmoid(s);
        }
    }
}

// ---------------------------------------------------------------------------
extern "C" void kernel_launch(void* const* d_in, const int* in_sizes, int n_in,
                              void* d_out, int out_size) {
    const float* x    = (const float*)d_in[0];
    const int*   ei   = (const int*)d_in[1];
    const float* ew   = (const float*)d_in[2];
    const float* Wxz  = (const float*)d_in[3];
    const float* bxz  = (const float*)d_in[4];
    const float* bhz  = (const float*)d_in[6];
    const float* Wxh  = (const float*)d_in[11];
    const float* bxh  = (const float*)d_in[12];
    const float* bhh  = (const float*)d_in[14];
    const float* Wlin = (const float*)d_in[15];
    const float* blin = (const float*)d_in[16];
    float* out = (float*)d_out;

    int n  = in_sizes[0] / FH;
    int ne = in_sizes[2];
    const int* row = ei;
    const int* col = ei + ne;

    cudaFuncSetAttribute(k_final, cudaFuncAttributeMaxDynamicSharedMemorySize, SMEM_BYTES);

    // Zero scratch via memset nodes (no kernel launch cost, full HBM BW)
    void* p_tx1;  cudaGetSymbolAddress(&p_tx1, g_tx1);
    void* p_p2;   cudaGetSymbolAddress(&p_p2, g_p2);
    void* p_deg;  cudaGetSymbolAddress(&p_deg, g_deg);
    cudaMemsetAsync(p_tx1, 0, (size_t)n * FH * sizeof(float), 0);
    cudaMemsetAsync(p_p2,  0, (size_t)n * FH * sizeof(float), 0);
    cudaMemsetAsync(p_deg, 0, (size_t)n * sizeof(float), 0);

    int nbDeg = (ne + 255) >> 8;
    k_deg_comb<<<nbDeg + 96, 256>>>(row, ew, ne, Wxz, Wxh);
    k_prop0<<<(ne * 4 + 255) / 256, 256>>>(x, row, col, ew, ne);
    k_prop1<<<(ne * 4 + 255) / 256, 256>>>(row, col, ne);
    k_final<<<(n + 127) / 128, 256, SMEM_BYTES>>>(x, bxz, bhz, bxh, bhh, Wlin, blin, out, n);
}

// round 7
// speedup vs baseline: 1.1343x; 1.1343x over previous
#include <cuda_runtime.h>
#include <cstdint>

#define NN_MAX 50000
#define NE_MAX 800000
#define FH 64

// Scratch
__device__ float g_deg[NN_MAX];
__device__ float g_norm[NE_MAX];
__device__ float g_tx1[NN_MAX * FH];
__device__ float g_p2[NN_MAX * FH];
__device__ float g_Wc[192 * 136];   // combined weights, [k][n] stride 136, tf32-rounded

__device__ __forceinline__ void red_add_v4(float* a, float x, float y, float z, float w) {
    asm volatile("red.global.add.v4.f32 [%0], {%1,%2,%3,%4};"
                 :: "l"(a), "f"(x), "f"(y), "f"(z), "f"(w) : "memory");
}
__device__ __forceinline__ uint32_t f2tf32(float f) {
    uint32_t u;
    asm("cvt.rna.tf32.f32 %0, %1;" : "=r"(u) : "f"(f));
    return u;
}
__device__ __forceinline__ float fast_sigmoid(float x) { return 1.f / (1.f + __expf(-x)); }
__device__ __forceinline__ float fast_tanh(float x) {
    float t = __expf(-2.f * fabsf(x));
    float r = (1.f - t) / (1.f + t);
    return copysignf(r, x);
}

// ---------------------------------------------------------------------------
// Fused: blocks [0, nbDeg) do degree atomics; blocks [nbDeg, ...) build g_Wc.
__global__ void k_deg_comb(const int* __restrict__ row, const float* __restrict__ w, int ne,
                           const float* __restrict__ Wxz, const float* __restrict__ Wxh) {
    int nbDeg = (ne + 255) >> 8;
    if ((int)blockIdx.x < nbDeg) {
        int e = blockIdx.x * 256 + threadIdx.x;
        if (e < ne) atomicAdd(g_deg + row[e], w[e]);
    } else {
        int t = (blockIdx.x - nbDeg) * 256 + threadIdx.x;
        if (t < 192 * 128) {
            int k = t >> 7, j = t & 127;
            const float* W = (j < 64) ? Wxz : Wxh;
            int jj = j & 63;
            float v;
            if (k < 64)       v = W[k * 64 + jj] - W[2 * 4096 + k * 64 + jj];
            else if (k < 128) v = W[4096 + (k - 64) * 64 + jj];
            else              v = 2.f * W[2 * 4096 + (k - 128) * 64 + jj];
            g_Wc[k * 136 + j] = __uint_as_float(f2tf32(v));
        }
    }
}

// norm[e] once per edge
__global__ void k_norm(const int* __restrict__ row, const int* __restrict__ col,
                       const float* __restrict__ w, int ne) {
    int e = blockIdx.x * blockDim.x + threadIdx.x;
    if (e < ne) {
        float dr = g_deg[row[e]], dc = g_deg[col[e]];
        float ir = dr > 0.f ? rsqrtf(dr) : 0.f;
        float ic = dc > 0.f ? rsqrtf(dc) : 0.f;
        g_norm[e] = -ir * w[e] * ic;
    }
}

// Propagation: 4 threads/edge, each thread handles 4 float4 quads.
// pass 0: x -> tx1 ; pass 1: tx1 -> p2
__global__ void k_prop(const float* __restrict__ xsrc, int pass,
                       const int* __restrict__ row, const int* __restrict__ col, int ne) {
    int t = blockIdx.x * blockDim.x + threadIdx.x;
    int e = t >> 2, q = t & 3;
    if (e >= ne) return;
    const float* src = pass ? g_tx1 : xsrc;
    float* dst = pass ? g_p2 : g_tx1;
    float nm = g_norm[e];
    int r = row[e], c = col[e];
    const float* sr = src + r * FH;
    float* dr = dst + c * FH;
    float4 v0 = *(const float4*)(sr + (q)      * 4);
    float4 v1 = *(const float4*)(sr + (q + 4)  * 4);
    float4 v2 = *(const float4*)(sr + (q + 8)  * 4);
    float4 v3 = *(const float4*)(sr + (q + 12) * 4);
    red_add_v4(dr + (q)      * 4, nm * v0.x, nm * v0.y, nm * v0.z, nm * v0.w);
    red_add_v4(dr + (q + 4)  * 4, nm * v1.x, nm * v1.y, nm * v1.z, nm * v1.w);
    red_add_v4(dr + (q + 8)  * 4, nm * v2.x, nm * v2.y, nm * v2.z, nm * v2.w);
    red_add_v4(dr + (q + 12) * 4, nm * v3.x, nm * v3.y, nm * v3.z, nm * v3.w);
}

// ---------------------------------------------------------------------------
// k_final: per block 128 nodes; A in smem (99KB, 2 blocks/SM),
// B fragments loaded directly from g_Wc (L2-resident) via __ldg.
#define A_STR 196
#define B_STR 136
#define Y_STR 132
#define SM_BZ   0
#define SM_BH   256
#define SM_WLIN 512
#define SM_A    1024
#define SMEM_BYTES (SM_A + 128 * A_STR * 4)   // 101376 B

__device__ __forceinline__ void mma8(float* c, const uint32_t* a, const uint32_t* b) {
    asm volatile("mma.sync.aligned.m16n8k8.row.col.f32.tf32.tf32.f32 "
                 "{%0,%1,%2,%3}, {%4,%5,%6,%7}, {%8,%9}, {%0,%1,%2,%3};"
                 : "+f"(c[0]), "+f"(c[1]), "+f"(c[2]), "+f"(c[3])
                 : "r"(a[0]), "r"(a[1]), "r"(a[2]), "r"(a[3]), "r"(b[0]), "r"(b[1]));
}

__global__ void __launch_bounds__(256, 2)
k_final(const float* __restrict__ x,
        const float* __restrict__ bxz, const float* __restrict__ bhz,
        const float* __restrict__ bxh, const float* __restrict__ bhh,
        const float* __restrict__ Wlin, const float* __restrict__ blin,
        float* __restrict__ out, int n) {
    extern __shared__ __align__(16) char smem[];
    float* sBz = (float*)(smem + SM_BZ);
    float* sBh = (float*)(smem + SM_BH);
    float* sWl = (float*)(smem + SM_WLIN);
    float* As  = (float*)(smem + SM_A);
    const uint32_t* Au = (const uint32_t*)As;
    const uint32_t* Bg = (const uint32_t*)g_Wc;

    int tid = threadIdx.x, wid = tid >> 5, lane = tid & 31;
    int blk = blockIdx.x;

    // Stage A with tf32 rounding: row m = node, k = [x|tx1|p2]
    for (int idx = tid; idx < 128 * 48; idx += 256) {
        int m = idx / 48, seg = idx % 48;
        int g = blk * 128 + m;
        float4 v = make_float4(0.f, 0.f, 0.f, 0.f);
        if (g < n) {
            const float* src = (seg < 16) ? (x + g * FH + seg * 4)
                             : (seg < 32) ? (g_tx1 + g * FH + (seg - 16) * 4)
                                          : (g_p2 + g * FH + (seg - 32) * 4);
            v = *(const float4*)src;
        }
        float4 o;
        o.x = __uint_as_float(f2tf32(v.x));
        o.y = __uint_as_float(f2tf32(v.y));
        o.z = __uint_as_float(f2tf32(v.z));
        o.w = __uint_as_float(f2tf32(v.w));
        *(float4*)(As + m * A_STR + seg * 4) = o;
    }

    if (tid < 64) {
        sBz[tid] = bxz[tid] + bhz[tid];
        sBh[tid] = bxh[tid] + bhh[tid];
    }
    if (tid < 128) sWl[tid] = Wlin[tid];
    __syncthreads();

    int mw = wid >> 2, nw = wid & 3;
    int g8 = lane >> 2, t4 = lane & 3;
    int m0 = mw * 64, n0 = nw * 32;

    float acc[4][4][4];
    #pragma unroll
    for (int mt = 0; mt < 4; ++mt)
        #pragma unroll
        for (int nt = 0; nt < 4; ++nt)
            #pragma unroll
            for (int e = 0; e < 4; ++e) acc[mt][nt][e] = 0.f;

    // Preload first B fragment set
    uint32_t b[4][2];
    #pragma unroll
    for (int nt = 0; nt < 4; ++nt) {
        int c0 = n0 + nt * 8;
        b[nt][0] = __ldg(Bg + (t4)     * B_STR + c0 + g8);
        b[nt][1] = __ldg(Bg + (t4 + 4) * B_STR + c0 + g8);
    }

    #pragma unroll
    for (int ks = 0; ks < 24; ++ks) {
        int k0 = ks * 8;
        uint32_t a[4][4];
        #pragma unroll
        for (int mt = 0; mt < 4; ++mt) {
            int r0 = m0 + mt * 16;
            a[mt][0] = Au[(r0 + g8)     * A_STR + k0 + t4];
            a[mt][1] = Au[(r0 + g8 + 8) * A_STR + k0 + t4];
            a[mt][2] = Au[(r0 + g8)     * A_STR + k0 + t4 + 4];
            a[mt][3] = Au[(r0 + g8 + 8) * A_STR + k0 + t4 + 4];
        }
        uint32_t bc[4][2];
        #pragma unroll
        for (int nt = 0; nt < 4; ++nt) {
            bc[nt][0] = b[nt][0];
            bc[nt][1] = b[nt][1];
        }
        if (ks < 23) {
            int k1 = k0 + 8;
            #pragma unroll
            for (int nt = 0; nt < 4; ++nt) {
                int c0 = n0 + nt * 8;
                b[nt][0] = __ldg(Bg + (k1 + t4)     * B_STR + c0 + g8);
                b[nt][1] = __ldg(Bg + (k1 + t4 + 4) * B_STR + c0 + g8);
            }
        }
        #pragma unroll
        for (int mt = 0; mt < 4; ++mt)
            #pragma unroll
            for (int nt = 0; nt < 4; ++nt)
                mma8(acc[mt][nt], a[mt], bc[nt]);
    }
    __syncthreads();

    float* Ys = As;   // reuse A region
    #pragma unroll
    for (int mt = 0; mt < 4; ++mt) {
        #pragma unroll
        for (int nt = 0; nt < 4; ++nt) {
            int r = m0 + mt * 16 + g8;
            int c = n0 + nt * 8 + 2 * t4;
            Ys[r * Y_STR + c]           = acc[mt][nt][0];
            Ys[r * Y_STR + c + 1]       = acc[mt][nt][1];
            Ys[(r + 8) * Y_STR + c]     = acc[mt][nt][2];
            Ys[(r + 8) * Y_STR + c + 1] = acc[mt][nt][3];
        }
    }
    __syncthreads();

    for (int t = tid; t < 128 * 64; t += 256) {
        int i = t >> 6, j = t & 63;
        float cz = Ys[i * Y_STR + j]      + sBz[j];
        float ch = Ys[i * Y_STR + 64 + j] + sBh[j];
        float z  = fast_sigmoid(cz);
        float ht = fast_tanh(ch);
        Ys[i * Y_STR + j] = fast_tanh((1.f - z) * ht);
    }
    __syncthreads();

    {
        int i = tid >> 1, c = tid & 1;
        int g = blk * 128 + i;
        if (g < n) {
            float s = blin[c];
            #pragma unroll 8
            for (int jj = 0; jj < 64; ++jj)
                s = fmaf(Ys[i * Y_STR + jj], sWl[2 * jj + c], s);
            out[g * 2 + c] = fast_sigmoid(s);
        }
    }
}

// ---------------------------------------------------------------------------
extern "C" void kernel_launch(void* const* d_in, const int* in_sizes, int n_in,
                              void* d_out, int out_size) {
    const float* x    = (const float*)d_in[0];
    const int*   ei   = (const int*)d_in[1];
    const float* ew   = (const float*)d_in[2];
    const float* Wxz  = (const float*)d_in[3];
    const float* bxz  = (const float*)d_in[4];
    const float* bhz  = (const float*)d_in[6];
    const float* Wxh  = (const float*)d_in[11];
    const float* bxh  = (const float*)d_in[12];
    const float* bhh  = (const float*)d_in[14];
    const float* Wlin = (const float*)d_in[15];
    const float* blin = (const float*)d_in[16];
    float* out = (float*)d_out;

    int n  = in_sizes[0] / FH;
    int ne = in_sizes[2];
    const int* row = ei;
    const int* col = ei + ne;

    cudaFuncSetAttribute(k_final, cudaFuncAttributeMaxDynamicSharedMemorySize, SMEM_BYTES);

    void* p_tx1;  cudaGetSymbolAddress(&p_tx1, g_tx1);
    void* p_p2;   cudaGetSymbolAddress(&p_p2, g_p2);
    void* p_deg;  cudaGetSymbolAddress(&p_deg, g_deg);
    cudaMemsetAsync(p_tx1, 0, (size_t)n * FH * sizeof(float), 0);
    cudaMemsetAsync(p_p2,  0, (size_t)n * FH * sizeof(float), 0);
    cudaMemsetAsync(p_deg, 0, (size_t)n * sizeof(float), 0);

    int nbDeg = (ne + 255) >> 8;
    k_deg_comb<<<nbDeg + 96, 256>>>(row, ew, ne, Wxz, Wxh);
    k_norm<<<(ne + 255) / 256, 256>>>(row, col, ew, ne);
    k_prop<<<(ne * 4 + 255) / 256, 256>>>(x, 0, row, col, ne);
    k_prop<<<(ne * 4 + 255) / 256, 256>>>(x, 1, row, col, ne);
    k_final<<<(n + 127) / 128, 256, SMEM_BYTES>>>(x, bxz, bhz, bxh, bhh, Wlin, blin, out, n);
}

// round 8
// speedup vs baseline: 1.4456x; 1.2744x over previous
#include <cuda_runtime.h>
#include <cstdint>

#define NN_MAX 50000
#define NE_MAX 800000
#define FH 64
#define SCAN_BLK 256

// Scratch
__device__ float  g_deg[NN_MAX];
__device__ int    g_cnt[NN_MAX];
__device__ int    g_start[NN_MAX];
__device__ int    g_cursor[NN_MAX];
__device__ int    g_bsum[SCAN_BLK];
__device__ int    g_boff[SCAN_BLK];
__device__ float2 g_es[NE_MAX];      // (row-bits, norm) bucketed by destination col
__device__ float  g_tx1[NN_MAX * FH];
__device__ float  g_p2[NN_MAX * FH];
__device__ float  g_Wc[192 * 136];   // combined weights, [k][n] stride 136, tf32

__device__ __forceinline__ uint32_t f2tf32(float f) {
    uint32_t u;
    asm("cvt.rna.tf32.f32 %0, %1;" : "=r"(u) : "f"(f));
    return u;
}
__device__ __forceinline__ float fast_sigmoid(float x) { return 1.f / (1.f + __expf(-x)); }
__device__ __forceinline__ float fast_tanh(float x) {
    float t = __expf(-2.f * fabsf(x));
    float r = (1.f - t) / (1.f + t);
    return copysignf(r, x);
}

// ---------------------------------------------------------------------------
// Fused: deg[row]+=w, cnt[col]+=1, and combined-weight build.
__global__ void k_degcnt_comb(const int* __restrict__ row, const int* __restrict__ col,
                              const float* __restrict__ w, int ne,
                              const float* __restrict__ Wxz, const float* __restrict__ Wxh) {
    int nbDeg = (ne + 255) >> 8;
    if ((int)blockIdx.x < nbDeg) {
        int e = blockIdx.x * 256 + threadIdx.x;
        if (e < ne) {
            atomicAdd(g_deg + row[e], w[e]);
            atomicAdd(g_cnt + col[e], 1);
        }
    } else {
        int t = (blockIdx.x - nbDeg) * 256 + threadIdx.x;
        if (t < 192 * 128) {
            int k = t >> 7, j = t & 127;
            const float* W = (j < 64) ? Wxz : Wxh;
            int jj = j & 63;
            float v;
            if (k < 64)       v = W[k * 64 + jj] - W[2 * 4096 + k * 64 + jj];
            else if (k < 128) v = W[4096 + (k - 64) * 64 + jj];
            else              v = 2.f * W[2 * 4096 + (k - 128) * 64 + jj];
            g_Wc[k * 136 + j] = __uint_as_float(f2tf32(v));
        }
    }
}

// ---- exclusive scan of cnt -> start (n <= 65536) ----
__global__ void k_scan1(int n) {
    __shared__ int s[SCAN_BLK];
    int i = blockIdx.x * SCAN_BLK + threadIdx.x;
    int v = (i < n) ? g_cnt[i] : 0;
    s[threadIdx.x] = v; __syncthreads();
    for (int o = SCAN_BLK / 2; o > 0; o >>= 1) {
        if (threadIdx.x < o) s[threadIdx.x] += s[threadIdx.x + o];
        __syncthreads();
    }
    if (threadIdx.x == 0) g_bsum[blockIdx.x] = s[0];
}
__global__ void k_scan2(int nblk) {
    __shared__ int s[SCAN_BLK];
    int t = threadIdx.x;
    int v = (t < nblk) ? g_bsum[t] : 0;
    s[t] = v; __syncthreads();
    for (int o = 1; o < SCAN_BLK; o <<= 1) {
        int u = (t >= o) ? s[t - o] : 0;
        __syncthreads(); s[t] += u; __syncthreads();
    }
    g_boff[t] = s[t] - v;
}
__global__ void k_scan3(int n) {
    __shared__ int s[SCAN_BLK];
    int t = threadIdx.x;
    int i = blockIdx.x * SCAN_BLK + t;
    int v = (i < n) ? g_cnt[i] : 0;
    s[t] = v; __syncthreads();
    for (int o = 1; o < SCAN_BLK; o <<= 1) {
        int u = (t >= o) ? s[t - o] : 0;
        __syncthreads(); s[t] += u; __syncthreads();
    }
    if (i < n) {
        int st = g_boff[blockIdx.x] + s[t] - v;
        g_start[i] = st;
        g_cursor[i] = st;
    }
}

// Scatter edges into destination buckets; norm computed inline.
__global__ void k_scatter(const int* __restrict__ row, const int* __restrict__ col,
                          const float* __restrict__ w, int ne) {
    int e = blockIdx.x * blockDim.x + threadIdx.x;
    if (e >= ne) return;
    int r = row[e], c = col[e];
    float dr = g_deg[r], dc = g_deg[c];
    float ir = dr > 0.f ? rsqrtf(dr) : 0.f;
    float ic = dc > 0.f ? rsqrtf(dc) : 0.f;
    float nm = -ir * w[e] * ic;
    int pos = atomicAdd(g_cursor + c, 1);
    g_es[pos] = make_float2(__int_as_float(r), nm);
}

// Atomic-free gather prop: 16 threads/node, unroll-4 for MLP.
// pass 0: x -> tx1 ; pass 1: tx1 -> p2
__global__ void k_gather(const float* __restrict__ xsrc, int pass, int n) {
    int t = blockIdx.x * blockDim.x + threadIdx.x;
    int node = t >> 4, h = t & 15;
    if (node >= n) return;
    const float* src = pass ? g_tx1 : xsrc;
    float* dst = pass ? g_p2 : g_tx1;
    int beg = g_start[node], cnt = g_cnt[node];
    const float2* ep = g_es + beg;
    float4 acc = make_float4(0.f, 0.f, 0.f, 0.f);
    int k = 0;
    for (; k + 4 <= cnt; k += 4) {
        float2 e0 = ep[k], e1 = ep[k + 1], e2 = ep[k + 2], e3 = ep[k + 3];
        const float4* p0 = (const float4*)(src + (__float_as_int(e0.x) << 6)) + h;
        const float4* p1 = (const float4*)(src + (__float_as_int(e1.x) << 6)) + h;
        const float4* p2 = (const float4*)(src + (__float_as_int(e2.x) << 6)) + h;
        const float4* p3 = (const float4*)(src + (__float_as_int(e3.x) << 6)) + h;
        float4 v0 = *p0, v1 = *p1, v2 = *p2, v3 = *p3;
        acc.x = fmaf(e0.y, v0.x, acc.x); acc.y = fmaf(e0.y, v0.y, acc.y);
        acc.z = fmaf(e0.y, v0.z, acc.z); acc.w = fmaf(e0.y, v0.w, acc.w);
        acc.x = fmaf(e1.y, v1.x, acc.x); acc.y = fmaf(e1.y, v1.y, acc.y);
        acc.z = fmaf(e1.y, v1.z, acc.z); acc.w = fmaf(e1.y, v1.w, acc.w);
        acc.x = fmaf(e2.y, v2.x, acc.x); acc.y = fmaf(e2.y, v2.y, acc.y);
        acc.z = fmaf(e2.y, v2.z, acc.z); acc.w = fmaf(e2.y, v2.w, acc.w);
        acc.x = fmaf(e3.y, v3.x, acc.x); acc.y = fmaf(e3.y, v3.y, acc.y);
        acc.z = fmaf(e3.y, v3.z, acc.z); acc.w = fmaf(e3.y, v3.w, acc.w);
    }
    for (; k < cnt; ++k) {
        float2 e0 = ep[k];
        float4 v0 = *((const float4*)(src + (__float_as_int(e0.x) << 6)) + h);
        acc.x = fmaf(e0.y, v0.x, acc.x); acc.y = fmaf(e0.y, v0.y, acc.y);
        acc.z = fmaf(e0.y, v0.z, acc.z); acc.w = fmaf(e0.y, v0.w, acc.w);
    }
    *((float4*)(dst + node * FH) + h) = acc;
}

// ---------------------------------------------------------------------------
// k_final: per block 128 nodes; A in smem (99KB, 2 blocks/SM),
// B fragments loaded directly from g_Wc (L2-resident) via __ldg.
#define A_STR 196
#define B_STR 136
#define Y_STR 132
#define SM_BZ   0
#define SM_BH   256
#define SM_WLIN 512
#define SM_A    1024
#define SMEM_BYTES (SM_A + 128 * A_STR * 4)

__device__ __forceinline__ void mma8(float* c, const uint32_t* a, const uint32_t* b) {
    asm volatile("mma.sync.aligned.m16n8k8.row.col.f32.tf32.tf32.f32 "
                 "{%0,%1,%2,%3}, {%4,%5,%6,%7}, {%8,%9}, {%0,%1,%2,%3};"
                 : "+f"(c[0]), "+f"(c[1]), "+f"(c[2]), "+f"(c[3])
                 : "r"(a[0]), "r"(a[1]), "r"(a[2]), "r"(a[3]), "r"(b[0]), "r"(b[1]));
}

__global__ void __launch_bounds__(256, 2)
k_final(const float* __restrict__ x,
        const float* __restrict__ bxz, const float* __restrict__ bhz,
        const float* __restrict__ bxh, const float* __restrict__ bhh,
        const float* __restrict__ Wlin, const float* __restrict__ blin,
        float* __restrict__ out, int n) {
    extern __shared__ __align__(16) char smem[];
    float* sBz = (float*)(smem + SM_BZ);
    float* sBh = (float*)(smem + SM_BH);
    float* sWl = (float*)(smem + SM_WLIN);
    float* As  = (float*)(smem + SM_A);
    const uint32_t* Au = (const uint32_t*)As;
    const uint32_t* Bg = (const uint32_t*)g_Wc;

    int tid = threadIdx.x, wid = tid >> 5, lane = tid & 31;
    int blk = blockIdx.x;

    for (int idx = tid; idx < 128 * 48; idx += 256) {
        int m = idx / 48, seg = idx % 48;
        int g = blk * 128 + m;
        float4 v = make_float4(0.f, 0.f, 0.f, 0.f);
        if (g < n) {
            const float* src = (seg < 16) ? (x + g * FH + seg * 4)
                             : (seg < 32) ? (g_tx1 + g * FH + (seg - 16) * 4)
                                          : (g_p2 + g * FH + (seg - 32) * 4);
            v = *(const float4*)src;
        }
        float4 o;
        o.x = __uint_as_float(f2tf32(v.x));
        o.y = __uint_as_float(f2tf32(v.y));
        o.z = __uint_as_float(f2tf32(v.z));
        o.w = __uint_as_float(f2tf32(v.w));
        *(float4*)(As + m * A_STR + seg * 4) = o;
    }

    if (tid < 64) {
        sBz[tid] = bxz[tid] + bhz[tid];
        sBh[tid] = bxh[tid] + bhh[tid];
    }
    if (tid < 128) sWl[tid] = Wlin[tid];
    __syncthreads();

    int mw = wid >> 2, nw = wid & 3;
    int g8 = lane >> 2, t4 = lane & 3;
    int m0 = mw * 64, n0 = nw * 32;

    float acc[4][4][4];
    #pragma unroll
    for (int mt = 0; mt < 4; ++mt)
        #pragma unroll
        for (int nt = 0; nt < 4; ++nt)
            #pragma unroll
            for (int e = 0; e < 4; ++e) acc[mt][nt][e] = 0.f;

    uint32_t b[4][2];
    #pragma unroll
    for (int nt = 0; nt < 4; ++nt) {
        int c0 = n0 + nt * 8;
        b[nt][0] = __ldg(Bg + (t4)     * B_STR + c0 + g8);
        b[nt][1] = __ldg(Bg + (t4 + 4) * B_STR + c0 + g8);
    }

    #pragma unroll
    for (int ks = 0; ks < 24; ++ks) {
        int k0 = ks * 8;
        uint32_t a[4][4];
        #pragma unroll
        for (int mt = 0; mt < 4; ++mt) {
            int r0 = m0 + mt * 16;
            a[mt][0] = Au[(r0 + g8)     * A_STR + k0 + t4];
            a[mt][1] = Au[(r0 + g8 + 8) * A_STR + k0 + t4];
            a[mt][2] = Au[(r0 + g8)     * A_STR + k0 + t4 + 4];
            a[mt][3] = Au[(r0 + g8 + 8) * A_STR + k0 + t4 + 4];
        }
        uint32_t bc[4][2];
        #pragma unroll
        for (int nt = 0; nt < 4; ++nt) {
            bc[nt][0] = b[nt][0];
            bc[nt][1] = b[nt][1];
        }
        if (ks < 23) {
            int k1 = k0 + 8;
            #pragma unroll
            for (int nt = 0; nt < 4; ++nt) {
                int c0 = n0 + nt * 8;
                b[nt][0] = __ldg(Bg + (k1 + t4)     * B_STR + c0 + g8);
                b[nt][1] = __ldg(Bg + (k1 + t4 + 4) * B_STR + c0 + g8);
            }
        }
        #pragma unroll
        for (int mt = 0; mt < 4; ++mt)
            #pragma unroll
            for (int nt = 0; nt < 4; ++nt)
                mma8(acc[mt][nt], a[mt], bc[nt]);
    }
    __syncthreads();

    float* Ys = As;
    #pragma unroll
    for (int mt = 0; mt < 4; ++mt) {
        #pragma unroll
        for (int nt = 0; nt < 4; ++nt) {
            int r = m0 + mt * 16 + g8;
            int c = n0 + nt * 8 + 2 * t4;
            Ys[r * Y_STR + c]           = acc[mt][nt][0];
            Ys[r * Y_STR + c + 1]       = acc[mt][nt][1];
            Ys[(r + 8) * Y_STR + c]     = acc[mt][nt][2];
            Ys[(r + 8) * Y_STR + c + 1] = acc[mt][nt][3];
        }
    }
    __syncthreads();

    for (int t = tid; t < 128 * 64; t += 256) {
        int i = t >> 6, j = t & 63;
        float cz = Ys[i * Y_STR + j]      + sBz[j];
        float ch = Ys[i * Y_STR + 64 + j] + sBh[j];
        float z  = fast_sigmoid(cz);
        float ht = fast_tanh(ch);
        Ys[i * Y_STR + j] = fast_tanh((1.f - z) * ht);
    }
    __syncthreads();

    {
        int i = tid >> 1, c = tid & 1;
        int g = blk * 128 + i;
        if (g < n) {
            float s = blin[c];
            #pragma unroll 8
            for (int jj = 0; jj < 64; ++jj)
                s = fmaf(Ys[i * Y_STR + jj], sWl[2 * jj + c], s);
            out[g * 2 + c] = fast_sigmoid(s);
        }
    }
}

// ---------------------------------------------------------------------------
extern "C" void kernel_launch(void* const* d_in, const int* in_sizes, int n_in,
                              void* d_out, int out_size) {
    const float* x    = (const float*)d_in[0];
    const int*   ei   = (const int*)d_in[1];
    const float* ew   = (const float*)d_in[2];
    const float* Wxz  = (const float*)d_in[3];
    const float* bxz  = (const float*)d_in[4];
    const float* bhz  = (const float*)d_in[6];
    const float* Wxh  = (const float*)d_in[11];
    const float* bxh  = (const float*)d_in[12];
    const float* bhh  = (const float*)d_in[14];
    const float* Wlin = (const float*)d_in[15];
    const float* blin = (const float*)d_in[16];
    float* out = (float*)d_out;

    int n  = in_sizes[0] / FH;
    int ne = in_sizes[2];
    const int* row = ei;
    const int* col = ei + ne;
    int nblk = (n + SCAN_BLK - 1) / SCAN_BLK;
    int nbDeg = (ne + 255) >> 8;

    cudaFuncSetAttribute(k_final, cudaFuncAttributeMaxDynamicSharedMemorySize, SMEM_BYTES);

    void* p_deg;  cudaGetSymbolAddress(&p_deg, g_deg);
    void* p_cnt;  cudaGetSymbolAddress(&p_cnt, g_cnt);
    cudaMemsetAsync(p_deg, 0, (size_t)n * sizeof(float), 0);
    cudaMemsetAsync(p_cnt, 0, (size_t)n * sizeof(int), 0);

    k_degcnt_comb<<<nbDeg + 96, 256>>>(row, col, ew, ne, Wxz, Wxh);
    k_scan1<<<nblk, SCAN_BLK>>>(n);
    k_scan2<<<1, SCAN_BLK>>>(nblk);
    k_scan3<<<nblk, SCAN_BLK>>>(n);
    k_scatter<<<(ne + 255) / 256, 256>>>(row, col, ew, ne);
    k_gather<<<(n * 16 + 255) / 256, 256>>>(x, 0, n);
    k_gather<<<(n * 16 + 255) / 256, 256>>>(x, 1, n);
    k_final<<<(n + 127) / 128, 256, SMEM_BYTES>>>(x, bxz, bhz, bxh, bhh, Wlin, blin, out, n);
}

// round 9
// speedup vs baseline: 1.4975x; 1.0359x over previous
#include <cuda_runtime.h>
#include <cuda_fp16.h>
#include <cstdint>

#define NN_MAX 50000
#define NE_MAX 800000
#define FH 64
#define SCAN_BLK 256

// Scratch. deg|cnt|sync share one zeroed region (single memset node).
__device__ int    g_zr[2 * NN_MAX + 2];
#define G_DEG  ((float*)g_zr)
#define G_CNT  (g_zr + NN_MAX)
#define G_SYNC (g_zr + 2 * NN_MAX)     // [0]=done counter, [1]=flag
__device__ int    g_start[NN_MAX];
__device__ int    g_cursor[NN_MAX];
__device__ int    g_bsum[SCAN_BLK];
__device__ int    g_boff[SCAN_BLK];
__device__ float2 g_es[NE_MAX];        // (row-bits, norm) bucketed by dst col
__device__ uint2  g_tx1h[NN_MAX * 16]; // tx1 as fp16, 4 halves per uint2
__device__ uint2  g_p2h[NN_MAX * 16];  // p2 as fp16
__device__ float  g_Wc[192 * 136];     // combined weights [k][n] stride 136, tf32

__device__ __forceinline__ uint32_t f2tf32(float f) {
    uint32_t u;
    asm("cvt.rna.tf32.f32 %0, %1;" : "=r"(u) : "f"(f));
    return u;
}
__device__ __forceinline__ float fast_sigmoid(float x) { return 1.f / (1.f + __expf(-x)); }
__device__ __forceinline__ float fast_tanh(float x) {
    float t = __expf(-2.f * fabsf(x));
    float r = (1.f - t) / (1.f + t);
    return copysignf(r, x);
}
__device__ __forceinline__ uint2 pack_h4(float a, float b, float c, float d) {
    __half2 h0 = __floats2half2_rn(a, b);
    __half2 h1 = __floats2half2_rn(c, d);
    return make_uint2(*(uint32_t*)&h0, *(uint32_t*)&h1);
}
__device__ __forceinline__ float4 unpack_h4(uint2 u) {
    float2 a = __half22float2(*(__half2*)&u.x);
    float2 b = __half22float2(*(__half2*)&u.y);
    return make_float4(a.x, a.y, b.x, b.y);
}

// ---------------------------------------------------------------------------
// Fused: deg[row]+=w, cnt[col]+=1, and combined-weight build.
__global__ void k_degcnt_comb(const int* __restrict__ row, const int* __restrict__ col,
                              const float* __restrict__ w, int ne,
                              const float* __restrict__ Wxz, const float* __restrict__ Wxh) {
    int nbDeg = (ne + 255) >> 8;
    if ((int)blockIdx.x < nbDeg) {
        int e = blockIdx.x * 256 + threadIdx.x;
        if (e < ne) {
            atomicAdd(G_DEG + row[e], w[e]);
            atomicAdd(G_CNT + col[e], 1);
        }
    } else {
        int t = (blockIdx.x - nbDeg) * 256 + threadIdx.x;
        if (t < 192 * 128) {
            int k = t >> 7, j = t & 127;
            const float* W = (j < 64) ? Wxz : Wxh;
            int jj = j & 63;
            float v;
            if (k < 64)       v = W[k * 64 + jj] - W[2 * 4096 + k * 64 + jj];
            else if (k < 128) v = W[4096 + (k - 64) * 64 + jj];
            else              v = 2.f * W[2 * 4096 + (k - 128) * 64 + jj];
            g_Wc[k * 136 + j] = __uint_as_float(f2tf32(v));
        }
    }
}

// Single-kernel exclusive scan of cnt -> start/cursor.
// All blocks co-resident (low regs/smem); last-arriving block scans block sums,
// others spin on flag. n <= 65536, nblk <= 256.
__global__ void k_scan(int n, int nblk) {
    __shared__ int s[SCAN_BLK];
    __shared__ int sl;
    int t = threadIdx.x;
    int i = blockIdx.x * SCAN_BLK + t;
    int v = (i < n) ? G_CNT[i] : 0;

    // inclusive scan within block
    s[t] = v; __syncthreads();
    #pragma unroll
    for (int o = 1; o < SCAN_BLK; o <<= 1) {
        int u = (t >= o) ? s[t - o] : 0;
        __syncthreads(); s[t] += u; __syncthreads();
    }
    int incl = s[t];
    if (t == SCAN_BLK - 1) g_bsum[blockIdx.x] = incl;
    __threadfence();
    __syncthreads();

    if (t == 0) sl = (atomicAdd(G_SYNC + 0, 1) == nblk - 1) ? 1 : 0;
    __syncthreads();
    if (sl) {
        int bv = (t < nblk) ? g_bsum[t] : 0;
        s[t] = bv; __syncthreads();
        #pragma unroll
        for (int o = 1; o < SCAN_BLK; o <<= 1) {
            int u = (t >= o) ? s[t - o] : 0;
            __syncthreads(); s[t] += u; __syncthreads();
        }
        g_boff[t] = s[t] - bv;     // exclusive block offsets
        __threadfence();
        __syncthreads();
        if (t == 0) atomicExch(G_SYNC + 1, 1);
    }
    if (t == 0) { while (atomicAdd(G_SYNC + 1, 0) == 0) {} }
    __syncthreads();

    if (i < n) {
        int st = g_boff[blockIdx.x] + incl - v;
        g_start[i] = st;
        g_cursor[i] = st;
    }
}

// Scatter edges into destination buckets; norm computed inline.
__global__ void k_scatter(const int* __restrict__ row, const int* __restrict__ col,
                          const float* __restrict__ w, int ne) {
    int e = blockIdx.x * blockDim.x + threadIdx.x;
    if (e >= ne) return;
    int r = row[e], c = col[e];
    float dr = G_DEG[r], dc = G_DEG[c];
    float ir = dr > 0.f ? rsqrtf(dr) : 0.f;
    float ic = dc > 0.f ? rsqrtf(dc) : 0.f;
    float nm = -ir * w[e] * ic;
    int pos = atomicAdd(g_cursor + c, 1);
    g_es[pos] = make_float2(__int_as_float(r), nm);
}

// pass 0: gather fp32 x -> fp16 tx1. 16 threads/node, unroll-4 edges.
__global__ void k_gather0(const float* __restrict__ x, int n) {
    int t = blockIdx.x * blockDim.x + threadIdx.x;
    int node = t >> 4, h = t & 15;
    if (node >= n) return;
    int beg = g_start[node], cnt = G_CNT[node];
    const float2* ep = g_es + beg;
    float4 acc = make_float4(0.f, 0.f, 0.f, 0.f);
    int k = 0;
    for (; k + 4 <= cnt; k += 4) {
        float2 e0 = ep[k], e1 = ep[k + 1], e2 = ep[k + 2], e3 = ep[k + 3];
        float4 v0 = *((const float4*)(x + (__float_as_int(e0.x) << 6)) + h);
        float4 v1 = *((const float4*)(x + (__float_as_int(e1.x) << 6)) + h);
        float4 v2 = *((const float4*)(x + (__float_as_int(e2.x) << 6)) + h);
        float4 v3 = *((const float4*)(x + (__float_as_int(e3.x) << 6)) + h);
        acc.x = fmaf(e0.y, v0.x, acc.x); acc.y = fmaf(e0.y, v0.y, acc.y);
        acc.z = fmaf(e0.y, v0.z, acc.z); acc.w = fmaf(e0.y, v0.w, acc.w);
        acc.x = fmaf(e1.y, v1.x, acc.x); acc.y = fmaf(e1.y, v1.y, acc.y);
        acc.z = fmaf(e1.y, v1.z, acc.z); acc.w = fmaf(e1.y, v1.w, acc.w);
        acc.x = fmaf(e2.y, v2.x, acc.x); acc.y = fmaf(e2.y, v2.y, acc.y);
        acc.z = fmaf(e2.y, v2.z, acc.z); acc.w = fmaf(e2.y, v2.w, acc.w);
        acc.x = fmaf(e3.y, v3.x, acc.x); acc.y = fmaf(e3.y, v3.y, acc.y);
        acc.z = fmaf(e3.y, v3.z, acc.z); acc.w = fmaf(e3.y, v3.w, acc.w);
    }
    for (; k < cnt; ++k) {
        float2 e0 = ep[k];
        float4 v0 = *((const float4*)(x + (__float_as_int(e0.x) << 6)) + h);
        acc.x = fmaf(e0.y, v0.x, acc.x); acc.y = fmaf(e0.y, v0.y, acc.y);
        acc.z = fmaf(e0.y, v0.z, acc.z); acc.w = fmaf(e0.y, v0.w, acc.w);
    }
    g_tx1h[node * 16 + h] = pack_h4(acc.x, acc.y, acc.z, acc.w);
}

// pass 1: gather fp16 tx1 -> fp16 p2. 16 threads/node, 8B loads.
__global__ void k_gather1(int n) {
    int t = blockIdx.x * blockDim.x + threadIdx.x;
    int node = t >> 4, h = t & 15;
    if (node >= n) return;
    int beg = g_start[node], cnt = G_CNT[node];
    const float2* ep = g_es + beg;
    float4 acc = make_float4(0.f, 0.f, 0.f, 0.f);
    int k = 0;
    for (; k + 4 <= cnt; k += 4) {
        float2 e0 = ep[k], e1 = ep[k + 1], e2 = ep[k + 2], e3 = ep[k + 3];
        float4 v0 = unpack_h4(g_tx1h[(__float_as_int(e0.x) << 4) + h]);
        float4 v1 = unpack_h4(g_tx1h[(__float_as_int(e1.x) << 4) + h]);
        float4 v2 = unpack_h4(g_tx1h[(__float_as_int(e2.x) << 4) + h]);
        float4 v3 = unpack_h4(g_tx1h[(__float_as_int(e3.x) << 4) + h]);
        acc.x = fmaf(e0.y, v0.x, acc.x); acc.y = fmaf(e0.y, v0.y, acc.y);
        acc.z = fmaf(e0.y, v0.z, acc.z); acc.w = fmaf(e0.y, v0.w, acc.w);
        acc.x = fmaf(e1.y, v1.x, acc.x); acc.y = fmaf(e1.y, v1.y, acc.y);
        acc.z = fmaf(e1.y, v1.z, acc.z); acc.w = fmaf(e1.y, v1.w, acc.w);
        acc.x = fmaf(e2.y, v2.x, acc.x); acc.y = fmaf(e2.y, v2.y, acc.y);
        acc.z = fmaf(e2.y, v2.z, acc.z); acc.w = fmaf(e2.y, v2.w, acc.w);
        acc.x = fmaf(e3.y, v3.x, acc.x); acc.y = fmaf(e3.y, v3.y, acc.y);
        acc.z = fmaf(e3.y, v3.z, acc.z); acc.w = fmaf(e3.y, v3.w, acc.w);
    }
    for (; k < cnt; ++k) {
        float2 e0 = ep[k];
        float4 v0 = unpack_h4(g_tx1h[(__float_as_int(e0.x) << 4) + h]);
        acc.x = fmaf(e0.y, v0.x, acc.x); acc.y = fmaf(e0.y, v0.y, acc.y);
        acc.z = fmaf(e0.y, v0.z, acc.z); acc.w = fmaf(e0.y, v0.w, acc.w);
    }
    g_p2h[node * 16 + h] = pack_h4(acc.x, acc.y, acc.z, acc.w);
}

// ---------------------------------------------------------------------------
// k_final: per block 128 nodes; A in smem (99KB, 2 blocks/SM),
// B fragments loaded directly from g_Wc (L2-resident) via __ldg.
#define A_STR 196
#define B_STR 136
#define Y_STR 132
#define SM_BZ   0
#define SM_BH   256
#define SM_WLIN 512
#define SM_A    1024
#define SMEM_BYTES (SM_A + 128 * A_STR * 4)

__device__ __forceinline__ void mma8(float* c, const uint32_t* a, const uint32_t* b) {
    asm volatile("mma.sync.aligned.m16n8k8.row.col.f32.tf32.tf32.f32 "
                 "{%0,%1,%2,%3}, {%4,%5,%6,%7}, {%8,%9}, {%0,%1,%2,%3};"
                 : "+f"(c[0]), "+f"(c[1]), "+f"(c[2]), "+f"(c[3])
                 : "r"(a[0]), "r"(a[1]), "r"(a[2]), "r"(a[3]), "r"(b[0]), "r"(b[1]));
}

__global__ void __launch_bounds__(256, 2)
k_final(const float* __restrict__ x,
        const float* __restrict__ bxz, const float* __restrict__ bhz,
        const float* __restrict__ bxh, const float* __restrict__ bhh,
        const float* __restrict__ Wlin, const float* __restrict__ blin,
        float* __restrict__ out, int n) {
    extern __shared__ __align__(16) char smem[];
    float* sBz = (float*)(smem + SM_BZ);
    float* sBh = (float*)(smem + SM_BH);
    float* sWl = (float*)(smem + SM_WLIN);
    float* As  = (float*)(smem + SM_A);
    const uint32_t* Au = (const uint32_t*)As;
    const uint32_t* Bg = (const uint32_t*)g_Wc;

    int tid = threadIdx.x, wid = tid >> 5, lane = tid & 31;
    int blk = blockIdx.x;

    // Stage A with tf32 rounding: k = [x(fp32) | tx1(fp16) | p2(fp16)]
    for (int idx = tid; idx < 128 * 48; idx += 256) {
        int m = idx / 48, seg = idx % 48;
        int g = blk * 128 + m;
        float4 v = make_float4(0.f, 0.f, 0.f, 0.f);
        if (g < n) {
            if (seg < 16)      v = *(const float4*)(x + g * FH + seg * 4);
            else if (seg < 32) v = unpack_h4(g_tx1h[g * 16 + (seg - 16)]);
            else               v = unpack_h4(g_p2h[g * 16 + (seg - 32)]);
        }
        float4 o;
        o.x = __uint_as_float(f2tf32(v.x));
        o.y = __uint_as_float(f2tf32(v.y));
        o.z = __uint_as_float(f2tf32(v.z));
        o.w = __uint_as_float(f2tf32(v.w));
        *(float4*)(As + m * A_STR + seg * 4) = o;
    }

    if (tid < 64) {
        sBz[tid] = bxz[tid] + bhz[tid];
        sBh[tid] = bxh[tid] + bhh[tid];
    }
    if (tid < 128) sWl[tid] = Wlin[tid];
    __syncthreads();

    int mw = wid >> 2, nw = wid & 3;
    int g8 = lane >> 2, t4 = lane & 3;
    int m0 = mw * 64, n0 = nw * 32;

    float acc[4][4][4];
    #pragma unroll
    for (int mt = 0; mt < 4; ++mt)
        #pragma unroll
        for (int nt = 0; nt < 4; ++nt)
            #pragma unroll
            for (int e = 0; e < 4; ++e) acc[mt][nt][e] = 0.f;

    uint32_t b[4][2];
    #pragma unroll
    for (int nt = 0; nt < 4; ++nt) {
        int c0 = n0 + nt * 8;
        b[nt][0] = __ldg(Bg + (t4)     * B_STR + c0 + g8);
        b[nt][1] = __ldg(Bg + (t4 + 4) * B_STR + c0 + g8);
    }

    #pragma unroll
    for (int ks = 0; ks < 24; ++ks) {
        int k0 = ks * 8;
        uint32_t a[4][4];
        #pragma unroll
        for (int mt = 0; mt < 4; ++mt) {
            int r0 = m0 + mt * 16;
            a[mt][0] = Au[(r0 + g8)     * A_STR + k0 + t4];
            a[mt][1] = Au[(r0 + g8 + 8) * A_STR + k0 + t4];
            a[mt][2] = Au[(r0 + g8)     * A_STR + k0 + t4 + 4];
            a[mt][3] = Au[(r0 + g8 + 8) * A_STR + k0 + t4 + 4];
        }
        uint32_t bc[4][2];
        #pragma unroll
        for (int nt = 0; nt < 4; ++nt) {
            bc[nt][0] = b[nt][0];
            bc[nt][1] = b[nt][1];
        }
        if (ks < 23) {
            int k1 = k0 + 8;
            #pragma unroll
            for (int nt = 0; nt < 4; ++nt) {
                int c0 = n0 + nt * 8;
                b[nt][0] = __ldg(Bg + (k1 + t4)     * B_STR + c0 + g8);
                b[nt][1] = __ldg(Bg + (k1 + t4 + 4) * B_STR + c0 + g8);
            }
        }
        #pragma unroll
        for (int mt = 0; mt < 4; ++mt)
            #pragma unroll
            for (int nt = 0; nt < 4; ++nt)
                mma8(acc[mt][nt], a[mt], bc[nt]);
    }
    __syncthreads();

    float* Ys = As;
    #pragma unroll
    for (int mt = 0; mt < 4; ++mt) {
        #pragma unroll
        for (int nt = 0; nt < 4; ++nt) {
            int r = m0 + mt * 16 + g8;
            int c = n0 + nt * 8 + 2 * t4;
            Ys[r * Y_STR + c]           = acc[mt][nt][0];
            Ys[r * Y_STR + c + 1]       = acc[mt][nt][1];
            Ys[(r + 8) * Y_STR + c]     = acc[mt][nt][2];
            Ys[(r + 8) * Y_STR + c + 1] = acc[mt][nt][3];
        }
    }
    __syncthreads();

    for (int t = tid; t < 128 * 64; t += 256) {
        int i = t >> 6, j = t & 63;
        float cz = Ys[i * Y_STR + j]      + sBz[j];
        float ch = Ys[i * Y_STR + 64 + j] + sBh[j];
        float z  = fast_sigmoid(cz);
        float ht = fast_tanh(ch);
        Ys[i * Y_STR + j] = fast_tanh((1.f - z) * ht);
    }
    __syncthreads();

    {
        int i = tid >> 1, c = tid & 1;
        int g = blk * 128 + i;
        if (g < n) {
            float s = blin[c];
            #pragma unroll 8
            for (int jj = 0; jj < 64; ++jj)
                s = fmaf(Ys[i * Y_STR + jj], sWl[2 * jj + c], s);
            out[g * 2 + c] = fast_sigmoid(s);
        }
    }
}

// ---------------------------------------------------------------------------
extern "C" void kernel_launch(void* const* d_in, const int* in_sizes, int n_in,
                              void* d_out, int out_size) {
    const float* x    = (const float*)d_in[0];
    const int*   ei   = (const int*)d_in[1];
    const float* ew   = (const float*)d_in[2];
    const float* Wxz  = (const float*)d_in[3];
    const float* bxz  = (const float*)d_in[4];
    const float* bhz  = (const float*)d_in[6];
    const float* Wxh  = (const float*)d_in[11];
    const float* bxh  = (const float*)d_in[12];
    const float* bhh  = (const float*)d_in[14];
    const float* Wlin = (const float*)d_in[15];
    const float* blin = (const float*)d_in[16];
    float* out = (float*)d_out;

    int n  = in_sizes[0] / FH;
    int ne = in_sizes[2];
    const int* row = ei;
    const int* col = ei + ne;
    int nblk = (n + SCAN_BLK - 1) / SCAN_BLK;
    int nbDeg = (ne + 255) >> 8;

    cudaFuncSetAttribute(k_final, cudaFuncAttributeMaxDynamicSharedMemorySize, SMEM_BYTES);

    // One memset covers deg | cnt | sync counters
    void* p_zr;  cudaGetSymbolAddress(&p_zr, g_zr);
    cudaMemsetAsync(p_zr, 0, (size_t)(2 * NN_MAX + 2) * sizeof(int), 0);

    k_degcnt_comb<<<nbDeg + 96, 256>>>(row, col, ew, ne, Wxz, Wxh);
    k_scan<<<nblk, SCAN_BLK>>>(n, nblk);
    k_scatter<<<(ne + 255) / 256, 256>>>(row, col, ew, ne);
    k_gather0<<<(n * 16 + 255) / 256, 256>>>(x, n);
    k_gather1<<<(n * 16 + 255) / 256, 256>>>(n);
    k_final<<<(n + 127) / 128, 256, SMEM_BYTES>>>(x, bxz, bhz, bxh, bhh, Wlin, blin, out, n);
}

// round 10
// speedup vs baseline: 1.7125x; 1.1436x over previous
#include <cuda_runtime.h>
#include <cuda_fp16.h>
#include <cstdint>

#define NN_MAX 50000
#define NE_MAX 800000
#define FH 64
#define SCAN_BLK 256

// Scratch. deg|cnt|sync share one zeroed region (single memset node).
__device__ int    g_zr[2 * NN_MAX + 2];
#define G_DEG  ((float*)g_zr)
#define G_CNT  (g_zr + NN_MAX)
#define G_SYNC (g_zr + 2 * NN_MAX)
__device__ int    g_start[NN_MAX];
__device__ int    g_cursor[NN_MAX];
__device__ int    g_bsum[SCAN_BLK];
__device__ int    g_boff[SCAN_BLK];
__device__ float2 g_es[NE_MAX];         // (row-bits, norm) bucketed by dst col
__device__ uint2  g_xh[NN_MAX * 16];    // x as fp16
__device__ uint2  g_tx1h[NN_MAX * 16];  // tx1 as fp16
__device__ uint2  g_p2h[NN_MAX * 16];   // p2 as fp16
#define B_STRH 200
__device__ __half g_Wch[128 * B_STRH];  // combined weights fp16, [n][k] (k contiguous)

__device__ __forceinline__ float fast_sigmoid(float x) { return 1.f / (1.f + __expf(-x)); }
__device__ __forceinline__ float fast_tanh(float x) {
    float t = __expf(-2.f * fabsf(x));
    float r = (1.f - t) / (1.f + t);
    return copysignf(r, x);
}
__device__ __forceinline__ uint2 pack_h4(float a, float b, float c, float d) {
    __half2 h0 = __floats2half2_rn(a, b);
    __half2 h1 = __floats2half2_rn(c, d);
    return make_uint2(*(uint32_t*)&h0, *(uint32_t*)&h1);
}
__device__ __forceinline__ float4 unpack_h4(uint2 u) {
    float2 a = __half22float2(*(__half2*)&u.x);
    float2 b = __half22float2(*(__half2*)&u.y);
    return make_float4(a.x, a.y, b.x, b.y);
}

// ---------------------------------------------------------------------------
// Fused: deg/cnt histogram | combined-weight build (fp16) | x -> fp16 convert.
__global__ void k_prep(const int* __restrict__ row, const int* __restrict__ col,
                       const float* __restrict__ w, int ne, int n,
                       const float* __restrict__ Wxz, const float* __restrict__ Wxh,
                       const float* __restrict__ x) {
    int nbDeg = (ne + 255) >> 8;
    int bid = blockIdx.x;
    if (bid < nbDeg) {
        int e = bid * 256 + threadIdx.x;
        if (e < ne) {
            atomicAdd(G_DEG + row[e], w[e]);
            atomicAdd(G_CNT + col[e], 1);
        }
    } else if (bid < nbDeg + 96) {
        int t = (bid - nbDeg) * 256 + threadIdx.x;
        if (t < 192 * 128) {
            int k = t >> 7, j = t & 127;
            const float* W = (j < 64) ? Wxz : Wxh;
            int jj = j & 63;
            float v;
            if (k < 64)       v = W[k * 64 + jj] - W[2 * 4096 + k * 64 + jj];
            else if (k < 128) v = W[4096 + (k - 64) * 64 + jj];
            else              v = 2.f * W[2 * 4096 + (k - 128) * 64 + jj];
            g_Wch[j * B_STRH + k] = __float2half_rn(v);
        }
    } else {
        int t = (bid - nbDeg - 96) * 256 + threadIdx.x;
        if (t < n * 16) {
            float4 v = ((const float4*)x)[t];
            g_xh[t] = pack_h4(v.x, v.y, v.z, v.w);
        }
    }
}

// Single-kernel exclusive scan of cnt -> start/cursor (spin on last block).
__global__ void k_scan(int n, int nblk) {
    __shared__ int s[SCAN_BLK];
    __shared__ int sl;
    int t = threadIdx.x;
    int i = blockIdx.x * SCAN_BLK + t;
    int v = (i < n) ? G_CNT[i] : 0;
    s[t] = v; __syncthreads();
    #pragma unroll
    for (int o = 1; o < SCAN_BLK; o <<= 1) {
        int u = (t >= o) ? s[t - o] : 0;
        __syncthreads(); s[t] += u; __syncthreads();
    }
    int incl = s[t];
    if (t == SCAN_BLK - 1) g_bsum[blockIdx.x] = incl;
    __threadfence();
    __syncthreads();
    if (t == 0) sl = (atomicAdd(G_SYNC + 0, 1) == nblk - 1) ? 1 : 0;
    __syncthreads();
    if (sl) {
        int bv = (t < nblk) ? g_bsum[t] : 0;
        s[t] = bv; __syncthreads();
        #pragma unroll
        for (int o = 1; o < SCAN_BLK; o <<= 1) {
            int u = (t >= o) ? s[t - o] : 0;
            __syncthreads(); s[t] += u; __syncthreads();
        }
        g_boff[t] = s[t] - bv;
        __threadfence();
        __syncthreads();
        if (t == 0) atomicExch(G_SYNC + 1, 1);
    }
    if (t == 0) { while (atomicAdd(G_SYNC + 1, 0) == 0) {} }
    __syncthreads();
    if (i < n) {
        int st = g_boff[blockIdx.x] + incl - v;
        g_start[i] = st;
        g_cursor[i] = st;
    }
}

// Scatter edges into destination buckets; norm computed inline.
__global__ void k_scatter(const int* __restrict__ row, const int* __restrict__ col,
                          const float* __restrict__ w, int ne) {
    int e = blockIdx.x * blockDim.x + threadIdx.x;
    if (e >= ne) return;
    int r = row[e], c = col[e];
    float dr = G_DEG[r], dc = G_DEG[c];
    float ir = dr > 0.f ? rsqrtf(dr) : 0.f;
    float ic = dc > 0.f ? rsqrtf(dc) : 0.f;
    float nm = -ir * w[e] * ic;
    int pos = atomicAdd(g_cursor + c, 1);
    g_es[pos] = make_float2(__int_as_float(r), nm);
}

// Gather prop (fp16 src -> fp16 dst): 16 threads/node, unroll-8 for MLP.
#define G_FMA(e, u) do { \
    float4 _v = unpack_h4(u); \
    acc.x = fmaf((e).y, _v.x, acc.x); acc.y = fmaf((e).y, _v.y, acc.y); \
    acc.z = fmaf((e).y, _v.z, acc.z); acc.w = fmaf((e).y, _v.w, acc.w); } while (0)

__global__ void k_gatherh(const uint2* __restrict__ src, uint2* __restrict__ dst, int n) {
    int t = blockIdx.x * blockDim.x + threadIdx.x;
    int node = t >> 4, h = t & 15;
    if (node >= n) return;
    int beg = g_start[node], cnt = G_CNT[node];
    const float2* ep = g_es + beg;
    float4 acc = make_float4(0.f, 0.f, 0.f, 0.f);
    int k = 0;
    for (; k + 8 <= cnt; k += 8) {
        float2 e0 = ep[k],     e1 = ep[k + 1], e2 = ep[k + 2], e3 = ep[k + 3];
        float2 e4 = ep[k + 4], e5 = ep[k + 5], e6 = ep[k + 6], e7 = ep[k + 7];
        uint2 u0 = src[(__float_as_int(e0.x) << 4) + h];
        uint2 u1 = src[(__float_as_int(e1.x) << 4) + h];
        uint2 u2 = src[(__float_as_int(e2.x) << 4) + h];
        uint2 u3 = src[(__float_as_int(e3.x) << 4) + h];
        uint2 u4 = src[(__float_as_int(e4.x) << 4) + h];
        uint2 u5 = src[(__float_as_int(e5.x) << 4) + h];
        uint2 u6 = src[(__float_as_int(e6.x) << 4) + h];
        uint2 u7 = src[(__float_as_int(e7.x) << 4) + h];
        G_FMA(e0, u0); G_FMA(e1, u1); G_FMA(e2, u2); G_FMA(e3, u3);
        G_FMA(e4, u4); G_FMA(e5, u5); G_FMA(e6, u6); G_FMA(e7, u7);
    }
    for (; k < cnt; ++k) {
        float2 e0 = ep[k];
        uint2 u0 = src[(__float_as_int(e0.x) << 4) + h];
        G_FMA(e0, u0);
    }
    dst[node * 16 + h] = pack_h4(acc.x, acc.y, acc.z, acc.w);
}

// ---------------------------------------------------------------------------
// k_final: 128 nodes/block; D[128x128] = A[128x192]@B via mma.m16n8k16.f16.
// A staged fp16 in smem (~51KB); B fragments __ldg from g_Wch (fp16, [n][k]).
#define A_STRH 200              // halves per A row (400B; word stride 100)
#define A_STRW 100
#define Y_STR 132
#define SM_BZ   0
#define SM_BH   256
#define SM_WLIN 512
#define SM_A    1024
#define SMEM_BYTES (SM_A + 128 * A_STRH * 2)   // 1024 + 51200 = 52224

__device__ __forceinline__ void mma16(float* c, const uint32_t* a, const uint32_t* b) {
    asm volatile("mma.sync.aligned.m16n8k16.row.col.f32.f16.f16.f32 "
                 "{%0,%1,%2,%3}, {%4,%5,%6,%7}, {%8,%9}, {%0,%1,%2,%3};"
                 : "+f"(c[0]), "+f"(c[1]), "+f"(c[2]), "+f"(c[3])
                 : "r"(a[0]), "r"(a[1]), "r"(a[2]), "r"(a[3]), "r"(b[0]), "r"(b[1]));
}

__global__ void __launch_bounds__(256, 2)
k_final(const float* __restrict__ bxz, const float* __restrict__ bhz,
        const float* __restrict__ bxh, const float* __restrict__ bhh,
        const float* __restrict__ Wlin, const float* __restrict__ blin,
        float* __restrict__ out, int n) {
    extern __shared__ __align__(16) char smem[];
    float* sBz = (float*)(smem + SM_BZ);
    float* sBh = (float*)(smem + SM_BH);
    float* sWl = (float*)(smem + SM_WLIN);
    char*  As  = smem + SM_A;
    const uint32_t* Au = (const uint32_t*)As;
    const uint32_t* Bg = (const uint32_t*)g_Wch;   // word index: n*100 + k/2

    int tid = threadIdx.x, wid = tid >> 5, lane = tid & 31;
    int blk = blockIdx.x;

    // Stage A (fp16 uint2 copies): row halves [0:64)=x, [64:128)=tx1, [128:192)=p2
    for (int idx = tid; idx < 128 * 48; idx += 256) {
        int m = idx / 48, seg = idx % 48;
        int g = blk * 128 + m;
        uint2 u = make_uint2(0u, 0u);
        if (g < n) {
            u = (seg < 16) ? g_xh[g * 16 + seg]
              : (seg < 32) ? g_tx1h[g * 16 + (seg - 16)]
                           : g_p2h[g * 16 + (seg - 32)];
        }
        *(uint2*)(As + m * 400 + seg * 8) = u;
    }

    if (tid < 64) {
        sBz[tid] = bxz[tid] + bhz[tid];
        sBh[tid] = bxh[tid] + bhh[tid];
    }
    if (tid < 128) sWl[tid] = Wlin[tid];
    __syncthreads();

    int mw = wid >> 2, nw = wid & 3;
    int g8 = lane >> 2, t4 = lane & 3;
    int m0 = mw * 64, n0 = nw * 32;

    float acc[4][4][4];
    #pragma unroll
    for (int mt = 0; mt < 4; ++mt)
        #pragma unroll
        for (int nt = 0; nt < 4; ++nt)
            #pragma unroll
            for (int e = 0; e < 4; ++e) acc[mt][nt][e] = 0.f;

    // Preload first B fragments
    uint32_t b[4][2];
    #pragma unroll
    for (int nt = 0; nt < 4; ++nt) {
        int cN = n0 + nt * 8 + g8;
        b[nt][0] = __ldg(Bg + cN * A_STRW + t4);
        b[nt][1] = __ldg(Bg + cN * A_STRW + 4 + t4);
    }

    #pragma unroll
    for (int ks = 0; ks < 12; ++ks) {
        int kw = ks * 8;                       // word offset (k0 = ks*16 halves)
        uint32_t a[4][4];
        #pragma unroll
        for (int mt = 0; mt < 4; ++mt) {
            int r0 = m0 + mt * 16;
            a[mt][0] = Au[(r0 + g8)     * A_STRW + kw + t4];
            a[mt][1] = Au[(r0 + g8 + 8) * A_STRW + kw + t4];
            a[mt][2] = Au[(r0 + g8)     * A_STRW + kw + 4 + t4];
            a[mt][3] = Au[(r0 + g8 + 8) * A_STRW + kw + 4 + t4];
        }
        uint32_t bc[4][2];
        #pragma unroll
        for (int nt = 0; nt < 4; ++nt) { bc[nt][0] = b[nt][0]; bc[nt][1] = b[nt][1]; }
        if (ks < 11) {
            int kw1 = kw + 8;
            #pragma unroll
            for (int nt = 0; nt < 4; ++nt) {
                int cN = n0 + nt * 8 + g8;
                b[nt][0] = __ldg(Bg + cN * A_STRW + kw1 + t4);
                b[nt][1] = __ldg(Bg + cN * A_STRW + kw1 + 4 + t4);
            }
        }
        #pragma unroll
        for (int mt = 0; mt < 4; ++mt)
            #pragma unroll
            for (int nt = 0; nt < 4; ++nt)
                mma16(acc[mt][nt], a[mt], bc[nt]);
    }
    __syncthreads();

    float* Ys = (float*)As;    // reuse (52KB < needed 67KB? no: 128*132*4=67.6KB)
    // NOTE: Y needs 128*Y_STR*4 = 67584 B > A region (51200). Use halves region +
    // extra: SMEM_BYTES accounts only 52224. Instead store Y as fp16 to fit.
    __half* Yh = (__half*)As;  // [128][A_STRH]
    #pragma unroll
    for (int mt = 0; mt < 4; ++mt) {
        #pragma unroll
        for (int nt = 0; nt < 4; ++nt) {
            int r = m0 + mt * 16 + g8;
            int c = n0 + nt * 8 + 2 * t4;
            __half2 lo = __floats2half2_rn(acc[mt][nt][0], acc[mt][nt][1]);
            __half2 hi = __floats2half2_rn(acc[mt][nt][2], acc[mt][nt][3]);
            *(__half2*)(Yh + r * A_STRH + c)       = lo;
            *(__half2*)(Yh + (r + 8) * A_STRH + c) = hi;
        }
    }
    __syncthreads();

    // Gates: th = tanh((1-sigmoid(cz)) * tanh(ch)), stored back as fp16
    for (int t = tid; t < 128 * 32; t += 256) {
        int i = t >> 5, j2 = (t & 31) * 2;
        float2 czv = __half22float2(*(__half2*)(Yh + i * A_STRH + j2));
        float2 chv = __half22float2(*(__half2*)(Yh + i * A_STRH + 64 + j2));
        float z0  = fast_sigmoid(czv.x + sBz[j2]);
        float z1  = fast_sigmoid(czv.y + sBz[j2 + 1]);
        float h0  = fast_tanh(chv.x + sBh[j2]);
        float h1  = fast_tanh(chv.y + sBh[j2 + 1]);
        float t0  = fast_tanh((1.f - z0) * h0);
        float t1  = fast_tanh((1.f - z1) * h1);
        *(__half2*)(Yh + i * A_STRH + j2) = __floats2half2_rn(t0, t1);
    }
    __syncthreads();

    // Head
    {
        int i = tid >> 1, c = tid & 1;
        int g = blk * 128 + i;
        if (g < n) {
            float s = blin[c];
            #pragma unroll 8
            for (int jj = 0; jj < 64; ++jj)
                s = fmaf(__half2float(Yh[i * A_STRH + jj]), sWl[2 * jj + c], s);
            out[g * 2 + c] = fast_sigmoid(s);
        }
    }
}

// ---------------------------------------------------------------------------
extern "C" void kernel_launch(void* const* d_in, const int* in_sizes, int n_in,
                              void* d_out, int out_size) {
    const float* x    = (const float*)d_in[0];
    const int*   ei   = (const int*)d_in[1];
    const float* ew   = (const float*)d_in[2];
    const float* Wxz  = (const float*)d_in[3];
    const float* bxz  = (const float*)d_in[4];
    const float* bhz  = (const float*)d_in[6];
    const float* Wxh  = (const float*)d_in[11];
    const float* bxh  = (const float*)d_in[12];
    const float* bhh  = (const float*)d_in[14];
    const float* Wlin = (const float*)d_in[15];
    const float* blin = (const float*)d_in[16];
    float* out = (float*)d_out;

    int n  = in_sizes[0] / FH;
    int ne = in_sizes[2];
    const int* row = ei;
    const int* col = ei + ne;
    int nblk  = (n + SCAN_BLK - 1) / SCAN_BLK;
    int nbDeg = (ne + 255) >> 8;
    int nbX   = (n * 16 + 255) >> 8;

    cudaFuncSetAttribute(k_final, cudaFuncAttributeMaxDynamicSharedMemorySize, SMEM_BYTES);

    void* p_zr;  cudaGetSymbolAddress(&p_zr, g_zr);
    cudaMemsetAsync(p_zr, 0, (size_t)(2 * NN_MAX + 2) * sizeof(int), 0);

    uint2 *p_xh, *p_tx1h, *p_p2h;
    cudaGetSymbolAddress((void**)&p_xh, g_xh);
    cudaGetSymbolAddress((void**)&p_tx1h, g_tx1h);
    cudaGetSymbolAddress((void**)&p_p2h, g_p2h);

    k_prep<<<nbDeg + 96 + nbX, 256>>>(row, col, ew, ne, n, Wxz, Wxh, x);
    k_scan<<<nblk, SCAN_BLK>>>(n, nblk);
    k_scatter<<<(ne + 255) / 256, 256>>>(row, col, ew, ne);
    k_gatherh<<<(n * 16 + 255) / 256, 256>>>(p_xh, p_tx1h, n);
    k_gatherh<<<(n * 16 + 255) / 256, 256>>>(p_tx1h, p_p2h, n);
    k_final<<<(n + 127) / 128, 256, SMEM_BYTES>>>(bxz, bhz, bxh, bhh, Wlin, blin, out, n);
}